// round 13
// baseline (speedup 1.0000x reference)
#include <cuda_runtime.h>
#include <cuda_bf16.h>

// loss = -(1/B) * sum_b [ 1 / (sum_j sigmoid(x[b,j] - x[b,0]) + 0.5) ]
// B = 32, N = 2048. Only row i=0 of the reference's [B,N,N] pair matrix is
// used, so compute the O(B*N) reduction directly.
//
// Measured-best composition (R5/R9/R11), with the R12 overflow fixed:
//  - single launch, 32 blocks x 256 threads, 2 front-batched float4 loads,
//  - per-thread sum quantized to 2^22 fixed point, ONE-instruction warp
//    reduce via redux.sync.add.s32 (redux.f32 is illegal on sm_103),
//  - block combine via smem array + one __syncthreads; the 8-warp total is
//    accumulated in 64-bit (block total can reach 2^33 — int32 overflowed
//    in R12 and produced rel_err 2.56),
//  - global combine: ONE relaxed packed atomicAdd(u64) — arrival count in
//    bits [46..), fixed-point partial (2^45 scale, +2^40 bias) below it.
//    Winner (old count == 31) gets the final sum from the RETURN VALUE,
//    writes out[0], resets g_acc -> device state is 0 after every launch
//    (graph-replay safe); integer accumulation at both levels makes the
//    output bit-deterministic.

#define RB 32  // batch count (grid size)

static __device__ unsigned long long g_acc = 0ULL;

// Global packing: bits [0,46) sum field, bits [46,..) arrival counter.
#define SUM_SHIFT 46
#define SUM_MASK  ((1ULL << SUM_SHIFT) - 1ULL)
#define FP_SCALE  35184372088832.0f   /* 2^45 */
#define FP_INV    (1.0 / 35184372088832.0)
#define FP_BIAS   (1LL << 40)         /* part >= -1/32 -> part*2^45 >= -2^40 */

// Per-thread quantization: s in (0,8) -> si <= 2^25; warp sum <= 2^30;
// block sum <= 2^33 (must be accumulated in 64-bit).
#define TQ_SCALE  4194304.0f          /* 2^22 */
#define TQ_INV    (1.0f / 4194304.0f)

static __global__ void __launch_bounds__(256) rankloss_fused_kernel(
    const float* __restrict__ x, float* __restrict__ out, float inv_B)
{
    const int b   = blockIdx.x;
    const int tid = threadIdx.x;
    const float* row = x + (size_t)b * 2048;

    const float x0 = __ldg(row);

    // 2048 floats = 512 float4; 256 threads -> 2 loads each, front-batched
    // (MLP=2) so the DRAM latencies overlap.
    const float4* row4 = reinterpret_cast<const float4*>(row);
    float4 v0 = __ldg(row4 + tid);
    float4 v1 = __ldg(row4 + tid + 256);

    // sigmoid(v - x0) = 1 / (1 + exp(x0 - v))
    float s = 0.0f;
    s += __fdividef(1.0f, 1.0f + __expf(x0 - v0.x));
    s += __fdividef(1.0f, 1.0f + __expf(x0 - v0.y));
    s += __fdividef(1.0f, 1.0f + __expf(x0 - v0.z));
    s += __fdividef(1.0f, 1.0f + __expf(x0 - v0.w));
    s += __fdividef(1.0f, 1.0f + __expf(x0 - v1.x));
    s += __fdividef(1.0f, 1.0f + __expf(x0 - v1.y));
    s += __fdividef(1.0f, 1.0f + __expf(x0 - v1.z));
    s += __fdividef(1.0f, 1.0f + __expf(x0 - v1.w));

    // Quantize, then one-instruction warp reduction (redux.sync.add.s32).
    int si = __float2int_rn(s * TQ_SCALE);
    int w  = __reduce_add_sync(0xFFFFFFFFu, si);

    __shared__ int warp_sums[8];
    const int warp = tid >> 5;
    const int lane = tid & 31;
    if (lane == 0) warp_sums[warp] = w;
    __syncthreads();

    if (tid == 0) {
        // 64-bit accumulation: block total can reach 2^33 (R12 bug: int32
        // wrapped here). Order-exact integer adds.
        long long ti = 0;
        #pragma unroll
        for (int i = 0; i < 8; i++)
            ti += (long long)warp_sums[i];

        float t = (float)ti * TQ_INV;               // row sum
        float part = -(1.0f / (t + 0.5f)) * inv_B;  // in [-1/32, 0)

        // Fixed-point encode + single packed global atomic.
        long long q = __float2ll_rn(part * FP_SCALE) + FP_BIAS;  // [0, 2^40]
        unsigned long long contrib =
            (1ULL << SUM_SHIFT) | (unsigned long long)q;
        unsigned long long old = atomicAdd(&g_acc, contrib);

        if ((old >> SUM_SHIFT) == (unsigned long long)(RB - 1)) {
            long long sum_q =
                (long long)((old & SUM_MASK) + (unsigned long long)q);
            double total = (double)(sum_q - (long long)RB * FP_BIAS) * FP_INV;
            out[0] = (float)total;
            // Reset for next replay; all blocks arrived, no race possible.
            asm volatile("st.relaxed.gpu.global.u64 [%0], %1;"
                         :: "l"(&g_acc), "l"(0ULL) : "memory");
        }
    }
}

extern "C" void kernel_launch(void* const* d_in, const int* in_sizes, int n_in,
                              void* d_out, int out_size) {
    const float* x = (const float*)d_in[0];
    float* out = (float*)d_out;

    const int total = in_sizes[0];   // B * N = 65536
    const int N = 2048;
    const int B = total / N;         // 32 == RB

    rankloss_fused_kernel<<<B, 256>>>(x, out, 1.0f / (float)B);
}